// round 3
// baseline (speedup 1.0000x reference)
#include <cuda_runtime.h>
#include <cstdint>

// Problem constants
#define SS 1024
#define BB 4
#define HH 16
#define DD 64
#define EE 1024
#define BHH 64   // B*H

// Scratch (device globals: allowed; no runtime allocation)
__device__ float g_q[BHH * SS * DD];     // [bh][s][d], pre-scaled by D^-0.5
__device__ float g_k[BHH * SS * DD];     // [bh][s][d]
__device__ float g_v[BHH * SS * DD];     // [bh][s][d]
__device__ float g_attn[SS * BB * EE];   // [s*B+b][h*64+d]

// XOR swizzle for 64x64 fp32 tiles, float4 granularity.
// word offset of the float4 group 'col4' (0..15) in row 'row' (0..63)
__device__ __forceinline__ int sw(int row, int col4) {
    return row * 64 + (((col4 ^ (row >> 2)) & 15) << 2);
}

// ---------------------------------------------------------------------------
// SGEMM 128x128x8, C[m][n] = sum_k A[m][k]*W[n][k] (+bias)
// MODE 0: A=x, W=W_in, scatter into g_q/g_k/g_v (q scaled by 1/8)
// MODE 1: A=g_attn, W=W_out, write d_out
// ---------------------------------------------------------------------------
template <int MODE, int NCOLS>
__global__ __launch_bounds__(256) void sgemm_kernel(
    const float* __restrict__ Ain, const float* __restrict__ W,
    const float* __restrict__ bias, float* __restrict__ Cout)
{
    __shared__ float As[8][128];
    __shared__ float Bs[8][128];
    const int K = 1024;

    const float* A = (MODE == 0) ? Ain : g_attn;

    int tid = threadIdx.x;
    int tx = tid & 15;        // col group
    int ty = tid >> 4;        // row group
    int bn = blockIdx.x;
    int bm = blockIdx.y;

    float acc[8][8];
#pragma unroll
    for (int i = 0; i < 8; i++)
#pragma unroll
        for (int j = 0; j < 8; j++) acc[i][j] = 0.f;

    int arow = tid >> 1;            // 0..127
    int akq  = (tid & 1) * 4;       // 0 or 4
    const float* Aptr = A + (size_t)(bm * 128 + arow) * K + akq;
    const float* Wptr = W + (size_t)(bn * 128 + arow) * K + akq;

    for (int k0 = 0; k0 < K; k0 += 8) {
        float4 av = *(const float4*)(Aptr + k0);
        float4 wv = *(const float4*)(Wptr + k0);
        __syncthreads();
        As[akq + 0][arow] = av.x;
        As[akq + 1][arow] = av.y;
        As[akq + 2][arow] = av.z;
        As[akq + 3][arow] = av.w;
        Bs[akq + 0][arow] = wv.x;
        Bs[akq + 1][arow] = wv.y;
        Bs[akq + 2][arow] = wv.z;
        Bs[akq + 3][arow] = wv.w;
        __syncthreads();
#pragma unroll
        for (int kk = 0; kk < 8; kk++) {
            float4 a0 = *(const float4*)&As[kk][ty * 8];
            float4 a1 = *(const float4*)&As[kk][ty * 8 + 4];
            float4 b0 = *(const float4*)&Bs[kk][tx * 4];
            float4 b1 = *(const float4*)&Bs[kk][tx * 4 + 64];
            float a[8] = {a0.x, a0.y, a0.z, a0.w, a1.x, a1.y, a1.z, a1.w};
            float b[8] = {b0.x, b0.y, b0.z, b0.w, b1.x, b1.y, b1.z, b1.w};
#pragma unroll
            for (int i = 0; i < 8; i++)
#pragma unroll
                for (int j = 0; j < 8; j++) acc[i][j] += a[i] * b[j];
        }
    }

    // epilogue
#pragma unroll
    for (int i = 0; i < 8; i++) {
        int r = bm * 128 + ty * 8 + i;
#pragma unroll
        for (int j = 0; j < 8; j++) {
            int c = bn * 128 + ((j < 4) ? (tx * 4 + j) : (64 + tx * 4 + j - 4));
            float v = acc[i][j] + bias[c];
            if (MODE == 0) {
                int sidx = r >> 2;        // s
                int b = r & 3;            // batch
                int h = c / 192;
                int rr = c - h * 192;
                int bh = b * HH + h;
                if (rr < 64) {
                    g_q[((size_t)bh * SS + sidx) * DD + rr] = v * 0.125f;
                } else if (rr < 128) {
                    g_k[((size_t)bh * SS + sidx) * DD + (rr - 64)] = v;
                } else {
                    g_v[((size_t)bh * SS + sidx) * DD + (rr - 128)] = v;
                }
            } else {
                Cout[(size_t)r * NCOLS + c] = v;
            }
        }
    }
}

// ---------------------------------------------------------------------------
// Flash attention with softmax_1 (phantom logit 0 -> init m=0, l=1),
// bias add, key-padding mask (int32!), post-softmax abm multiply.
// Block: 256 threads = 16(tx: k/d cols) x 16(ty: q rows), 4x4 per thread.
// Grid: (16 q-tiles, 64 bh)
// ---------------------------------------------------------------------------
__global__ __launch_bounds__(256) void attn_kernel(
    const float* __restrict__ attn_bias, const float* __restrict__ attn_mul,
    const int* __restrict__ kpm)
{
    __shared__ float Qt[64 * 64];     // swizzled, [d][q]
    __shared__ float KtPs[64 * 64];   // swizzled, [d][k] then reused as [k][q]
    __shared__ float Vs[64 * 64];     // natural [k][d]

    int qt = blockIdx.x;
    int bh = blockIdx.y;
    int b = bh >> 4;
    int h = bh & 15;
    int tid = threadIdx.x;
    int tx = tid & 15;
    int ty = tid >> 4;

    const float* qbase = g_q + ((size_t)bh * SS + qt * 64) * DD;
    const float* kbase = g_k + (size_t)bh * SS * DD;
    const float* vbase = g_v + (size_t)bh * SS * DD;
    const float* bbase = attn_bias + ((size_t)bh * SS + qt * 64) * SS;
    const float* mbase = attn_mul + ((size_t)bh * SS + qt * 64) * SS;
    const int* kp = kpm + b * SS;    // int32 mask (bool converted by harness)

    // Load Q tile transposed into Qt (swizzled)
#pragma unroll
    for (int t = 0; t < 4; t++) {
        int idx = tid + t * 256;
        int q = idx >> 4;
        int dg = (idx & 15) << 2;
        float4 v = *(const float4*)(qbase + (size_t)q * DD + dg);
        Qt[sw(dg + 0, q >> 2) + (q & 3)] = v.x;
        Qt[sw(dg + 1, q >> 2) + (q & 3)] = v.y;
        Qt[sw(dg + 2, q >> 2) + (q & 3)] = v.z;
        Qt[sw(dg + 3, q >> 2) + (q & 3)] = v.w;
    }

    float acc[4][4];
#pragma unroll
    for (int i = 0; i < 4; i++)
#pragma unroll
        for (int j = 0; j < 4; j++) acc[i][j] = 0.f;
    float mrow[4] = {0.f, 0.f, 0.f, 0.f};   // phantom logit 0
    float lrow[4] = {1.f, 1.f, 1.f, 1.f};   // exp(0-0)

    for (int kt = 0; kt < 16; kt++) {
        int k0 = kt * 64;
        __syncthreads();  // prior-iter Ps/Vs reads done (and Qt store on iter 0)

        // load K (transposed+swizzled) and V (natural)
#pragma unroll
        for (int t = 0; t < 4; t++) {
            int idx = tid + t * 256;
            int k = idx >> 4;
            int dg = (idx & 15) << 2;
            float4 kv = *(const float4*)(kbase + (size_t)(k0 + k) * DD + dg);
            KtPs[sw(dg + 0, k >> 2) + (k & 3)] = kv.x;
            KtPs[sw(dg + 1, k >> 2) + (k & 3)] = kv.y;
            KtPs[sw(dg + 2, k >> 2) + (k & 3)] = kv.z;
            KtPs[sw(dg + 3, k >> 2) + (k & 3)] = kv.w;
            float4 vv = *(const float4*)(vbase + (size_t)(k0 + k) * DD + dg);
            *(float4*)&Vs[k * 64 + dg] = vv;
        }
        // int32 key padding mask for this thread's 4 k-columns
        int4 mk = *(const int4*)(kp + k0 + tx * 4);
        __syncthreads();

        // S tile = bias, then += Q@K^T
        float sreg[4][4];
#pragma unroll
        for (int i = 0; i < 4; i++) {
            float4 bv = *(const float4*)(bbase + (size_t)(ty * 4 + i) * SS + k0 + tx * 4);
            sreg[i][0] = bv.x; sreg[i][1] = bv.y; sreg[i][2] = bv.z; sreg[i][3] = bv.w;
        }
#pragma unroll 8
        for (int d = 0; d < 64; d++) {
            float4 a = *(const float4*)&Qt[sw(d, ty)];
            float4 bb = *(const float4*)&KtPs[sw(d, tx)];
            sreg[0][0] += a.x * bb.x; sreg[0][1] += a.x * bb.y;
            sreg[0][2] += a.x * bb.z; sreg[0][3] += a.x * bb.w;
            sreg[1][0] += a.y * bb.x; sreg[1][1] += a.y * bb.y;
            sreg[1][2] += a.y * bb.z; sreg[1][3] += a.y * bb.w;
            sreg[2][0] += a.z * bb.x; sreg[2][1] += a.z * bb.y;
            sreg[2][2] += a.z * bb.z; sreg[2][3] += a.z * bb.w;
            sreg[3][0] += a.w * bb.x; sreg[3][1] += a.w * bb.y;
            sreg[3][2] += a.w * bb.z; sreg[3][3] += a.w * bb.w;
        }
        // key padding mask: masked -> -1e30 (exp underflows to 0)
        if (mk.x) { sreg[0][0] = sreg[1][0] = sreg[2][0] = sreg[3][0] = -1e30f; }
        if (mk.y) { sreg[0][1] = sreg[1][1] = sreg[2][1] = sreg[3][1] = -1e30f; }
        if (mk.z) { sreg[0][2] = sreg[1][2] = sreg[2][2] = sreg[3][2] = -1e30f; }
        if (mk.w) { sreg[0][3] = sreg[1][3] = sreg[2][3] = sreg[3][3] = -1e30f; }

        // online softmax stats per q-row (reduce over 16 tx lanes)
#pragma unroll
        for (int i = 0; i < 4; i++) {
            float tm = fmaxf(fmaxf(sreg[i][0], sreg[i][1]), fmaxf(sreg[i][2], sreg[i][3]));
            tm = fmaxf(tm, __shfl_xor_sync(0xffffffffu, tm, 1));
            tm = fmaxf(tm, __shfl_xor_sync(0xffffffffu, tm, 2));
            tm = fmaxf(tm, __shfl_xor_sync(0xffffffffu, tm, 4));
            tm = fmaxf(tm, __shfl_xor_sync(0xffffffffu, tm, 8));
            float mn = fmaxf(mrow[i], tm);
            float sc = __expf(mrow[i] - mn);
            mrow[i] = mn;
            float rs = 0.f;
#pragma unroll
            for (int j = 0; j < 4; j++) {
                float e = __expf(sreg[i][j] - mn);
                sreg[i][j] = e;
                rs += e;
            }
            rs += __shfl_xor_sync(0xffffffffu, rs, 1);
            rs += __shfl_xor_sync(0xffffffffu, rs, 2);
            rs += __shfl_xor_sync(0xffffffffu, rs, 4);
            rs += __shfl_xor_sync(0xffffffffu, rs, 8);
            lrow[i] = lrow[i] * sc + rs;
            acc[i][0] *= sc; acc[i][1] *= sc; acc[i][2] *= sc; acc[i][3] *= sc;
        }

        __syncthreads();  // everyone done reading K from KtPs

        // p = e * abm, store transposed into KtPs as Ps[k][q] (swizzled)
#pragma unroll
        for (int i = 0; i < 4; i++) {
            float4 mv = *(const float4*)(mbase + (size_t)(ty * 4 + i) * SS + k0 + tx * 4);
            sreg[i][0] *= mv.x; sreg[i][1] *= mv.y; sreg[i][2] *= mv.z; sreg[i][3] *= mv.w;
        }
#pragma unroll
        for (int j = 0; j < 4; j++) {
            float4 p4 = make_float4(sreg[0][j], sreg[1][j], sreg[2][j], sreg[3][j]);
            *(float4*)&KtPs[sw(tx * 4 + j, ty)] = p4;
        }
        __syncthreads();

        // acc += P @ V
#pragma unroll 8
        for (int kk = 0; kk < 64; kk++) {
            float4 p = *(const float4*)&KtPs[sw(kk, ty)];
            float4 vv = *(const float4*)&Vs[kk * 64 + tx * 4];
            acc[0][0] += p.x * vv.x; acc[0][1] += p.x * vv.y;
            acc[0][2] += p.x * vv.z; acc[0][3] += p.x * vv.w;
            acc[1][0] += p.y * vv.x; acc[1][1] += p.y * vv.y;
            acc[1][2] += p.y * vv.z; acc[1][3] += p.y * vv.w;
            acc[2][0] += p.z * vv.x; acc[2][1] += p.z * vv.y;
            acc[2][2] += p.z * vv.z; acc[2][3] += p.z * vv.w;
            acc[3][0] += p.w * vv.x; acc[3][1] += p.w * vv.y;
            acc[3][2] += p.w * vv.z; acc[3][3] += p.w * vv.w;
        }
    }

    // epilogue: out = acc / l, store as [s*B+b][h*64+d]
#pragma unroll
    for (int i = 0; i < 4; i++) {
        float inv = 1.0f / lrow[i];
        int r = (qt * 64 + ty * 4 + i) * BB + b;
        float4 o = make_float4(acc[i][0] * inv, acc[i][1] * inv,
                               acc[i][2] * inv, acc[i][3] * inv);
        *(float4*)&g_attn[(size_t)r * EE + h * 64 + tx * 4] = o;
    }
}

// ---------------------------------------------------------------------------
extern "C" void kernel_launch(void* const* d_in, const int* in_sizes, int n_in,
                              void* d_out, int out_size)
{
    (void)in_sizes; (void)n_in; (void)out_size;
    const float* x          = (const float*)d_in[0];
    const float* attn_bias  = (const float*)d_in[1];
    const float* attn_mul   = (const float*)d_in[2];
    const int*   kpm        = (const int*)d_in[3];
    const float* W_in       = (const float*)d_in[4];
    const float* b_in       = (const float*)d_in[5];
    const float* W_out      = (const float*)d_in[6];
    const float* b_out      = (const float*)d_in[7];
    float* out = (float*)d_out;

    dim3 g1(3072 / 128, 4096 / 128);
    sgemm_kernel<0, 3072><<<g1, 256>>>(x, W_in, b_in, nullptr);

    dim3 g2(16, BHH);
    attn_kernel<<<g2, 256>>>(attn_bias, attn_mul, kpm);

    dim3 g3(1024 / 128, 4096 / 128);
    sgemm_kernel<1, 1024><<<g3, 256>>>(nullptr, W_out, b_out, out);
}

// round 6
// speedup vs baseline: 1.7336x; 1.7336x over previous
#include <cuda_runtime.h>
#include <cuda_bf16.h>
#include <cstdint>

// Problem constants
#define SS 1024
#define BB 4
#define HH 16
#define DD 64
#define EE 1024
#define BHH 64   // B*H

// ---------------------------------------------------------------------------
// Scratch (device globals)
// ---------------------------------------------------------------------------
__device__ float g_q[BHH * SS * DD];     // [bh][s][d], pre-scaled by D^-0.5
__device__ float g_k[BHH * SS * DD];
__device__ float g_v[BHH * SS * DD];
__device__ float g_attn[SS * BB * EE];   // [s*B+b][h*64+d]

__device__ __nv_bfloat16 g_xhi[4096 * 1024], g_xlo[4096 * 1024];
__device__ __nv_bfloat16 g_wihi[3072 * 1024], g_wilo[3072 * 1024];
__device__ __nv_bfloat16 g_wohi[1024 * 1024], g_wolo[1024 * 1024];
__device__ __nv_bfloat16 g_ahi[4096 * 1024], g_alo[4096 * 1024];

// ---------------------------------------------------------------------------
// Warp-level MMA helpers (baseline PTX, works on sm_103 non-'a' target)
// ---------------------------------------------------------------------------
__device__ __forceinline__ uint32_t smem_u32(const void* p) {
    uint32_t a;
    asm("{ .reg .u64 t; cvta.to.shared.u64 t, %1; cvt.u32.u64 %0, t; }"
        : "=r"(a) : "l"(p));
    return a;
}

__device__ __forceinline__ void ldm_x4(uint32_t* r, uint32_t addr) {
    asm volatile("ldmatrix.sync.aligned.m8n8.x4.shared.b16 {%0,%1,%2,%3}, [%4];"
                 : "=r"(r[0]), "=r"(r[1]), "=r"(r[2]), "=r"(r[3]) : "r"(addr));
}
__device__ __forceinline__ void ldm_x2(uint32_t* r, uint32_t addr) {
    asm volatile("ldmatrix.sync.aligned.m8n8.x2.shared.b16 {%0,%1}, [%2];"
                 : "=r"(r[0]), "=r"(r[1]) : "r"(addr));
}

// D(f32) += A(bf16) @ B(bf16), m16n8k16
__device__ __forceinline__ void mma_bf16(float* c, const uint32_t* a, const uint32_t* b) {
    asm volatile(
        "mma.sync.aligned.m16n8k16.row.col.f32.bf16.bf16.f32 "
        "{%0,%1,%2,%3}, {%4,%5,%6,%7}, {%8,%9}, {%0,%1,%2,%3};"
        : "+f"(c[0]), "+f"(c[1]), "+f"(c[2]), "+f"(c[3])
        : "r"(a[0]), "r"(a[1]), "r"(a[2]), "r"(a[3]), "r"(b[0]), "r"(b[1]));
}

// ---------------------------------------------------------------------------
// fp32 -> bf16 hi/lo split conversion
// sel: 0 = x -> g_x*, 1 = W_in -> g_wi*, 2 = W_out -> g_wo*, 3 = g_attn -> g_a*
// ---------------------------------------------------------------------------
__global__ __launch_bounds__(256) void split_bf16(const float* __restrict__ in,
                                                  int sel, int n4) {
    int i = blockIdx.x * blockDim.x + threadIdx.x;
    if (i >= n4) return;
    __nv_bfloat16 *hi, *lo;
    const float* src = in;
    if (sel == 0)      { hi = g_xhi;  lo = g_xlo;  }
    else if (sel == 1) { hi = g_wihi; lo = g_wilo; }
    else if (sel == 2) { hi = g_wohi; lo = g_wolo; }
    else               { hi = g_ahi;  lo = g_alo;  src = g_attn; }

    float4 v = ((const float4*)src)[i];
    float vv[4] = {v.x, v.y, v.z, v.w};
    uint32_t h[4], l[4];
#pragma unroll
    for (int j = 0; j < 4; j++) {
        __nv_bfloat16 hb = __float2bfloat16(vv[j]);
        float r = vv[j] - __bfloat162float(hb);
        __nv_bfloat16 lb = __float2bfloat16(r);
        h[j] = (uint32_t)__bfloat16_as_ushort(hb);
        l[j] = (uint32_t)__bfloat16_as_ushort(lb);
    }
    ((uint2*)hi)[i] = make_uint2(h[0] | (h[1] << 16), h[2] | (h[3] << 16));
    ((uint2*)lo)[i] = make_uint2(l[0] | (l[1] << 16), l[2] | (l[3] << 16));
}

// ---------------------------------------------------------------------------
// mma.sync split-bf16 GEMM: C[m][n] = sum_k A[m][k]*W[n][k] (+bias)
//   C ~= AhiWhi + AhiWlo + AloWhi
// CTA 128x128, K-tile 32. 8 warps (2x4), warp tile 64x32, frag m16n8k16.
// Smem: 4 operand tiles, 128 rows x 4 chunks(16B), row pitch 5 chunks
// (odd stride -> ldmatrix 8-row fetches are bank-conflict-free).
// MODE 0: A=x(split), W=W_in(split), scatter into g_q/g_k/g_v (q * 0.125)
// MODE 1: A=g_attn(split), W=W_out(split), write d_out
// ---------------------------------------------------------------------------
template <int MODE>
__global__ __launch_bounds__(256) void gemm_mma(
    const float* __restrict__ bias, float* __restrict__ Cout)
{
    __shared__ __align__(16) uint4 sAhi[640], sAlo[640], sBhi[640], sBlo[640];

    const __nv_bfloat16* Ahi = (MODE == 0) ? g_xhi  : g_ahi;
    const __nv_bfloat16* Alo = (MODE == 0) ? g_xlo  : g_alo;
    const __nv_bfloat16* Bhi = (MODE == 0) ? g_wihi : g_wohi;
    const __nv_bfloat16* Blo = (MODE == 0) ? g_wilo : g_wolo;

    const int tid = threadIdx.x;
    const int lane = tid & 31;
    const int wid = tid >> 5;
    const int wm = wid >> 2;        // 0..1: warp row (64 rows)
    const int wn = wid & 3;         // 0..3: warp col (32 cols)
    const int bm = blockIdx.y, bn = blockIdx.x;
    const int K = 1024;

    float acc[4][4][4];
#pragma unroll
    for (int mf = 0; mf < 4; mf++)
#pragma unroll
        for (int nf = 0; nf < 4; nf++)
#pragma unroll
            for (int e = 0; e < 4; e++) acc[mf][nf][e] = 0.f;

    const uint32_t uAhi = smem_u32(sAhi), uAlo = smem_u32(sAlo);
    const uint32_t uBhi = smem_u32(sBhi), uBlo = smem_u32(sBlo);

    // ldmatrix lane->address components
    const int a_row = wm * 64 + (lane & 7) + ((lane >> 3) & 1) * 8;  // + mf*16
    const int a_kc  = (lane >> 4) & 1;                               // + ks*2
    const int b_row = wn * 32 + (lane & 7);                          // + nf*8
    const int b_kc  = (lane >> 3) & 1;                               // + ks*2

    for (int kt = 0; kt < 32; kt++) {
        const int k0 = kt * 32;

        // prefetch gmem (2 chunks of 16B per array per thread)
        uint4 va[2], vb[2], vc[2], vd[2];
#pragma unroll
        for (int q = 0; q < 2; q++) {
            int c = tid + q * 256;
            int row = c >> 2, kc = c & 3;
            size_t ao = (size_t)(bm * 128 + row) * K + k0 + kc * 8;
            size_t bo = (size_t)(bn * 128 + row) * K + k0 + kc * 8;
            va[q] = *(const uint4*)(Ahi + ao);
            vb[q] = *(const uint4*)(Alo + ao);
            vc[q] = *(const uint4*)(Bhi + bo);
            vd[q] = *(const uint4*)(Blo + bo);
        }
        __syncthreads();
#pragma unroll
        for (int q = 0; q < 2; q++) {
            int c = tid + q * 256;
            int row = c >> 2, kc = c & 3;
            int p = row * 5 + kc;
            sAhi[p] = va[q]; sAlo[p] = vb[q];
            sBhi[p] = vc[q]; sBlo[p] = vd[q];
        }
        __syncthreads();

#pragma unroll
        for (int ks = 0; ks < 2; ks++) {
            uint32_t ah[4][4], al[4][4], bh[4][2], bl[4][2];
#pragma unroll
            for (int mf = 0; mf < 4; mf++) {
                uint32_t off = (uint32_t)(((a_row + mf * 16) * 5 + ks * 2 + a_kc) * 16);
                ldm_x4(ah[mf], uAhi + off);
                ldm_x4(al[mf], uAlo + off);
            }
#pragma unroll
            for (int nf = 0; nf < 4; nf++) {
                uint32_t off = (uint32_t)(((b_row + nf * 8) * 5 + ks * 2 + b_kc) * 16);
                ldm_x2(bh[nf], uBhi + off);
                ldm_x2(bl[nf], uBlo + off);
            }
#pragma unroll
            for (int mf = 0; mf < 4; mf++)
#pragma unroll
                for (int nf = 0; nf < 4; nf++) {
                    mma_bf16(acc[mf][nf], ah[mf], bh[nf]);
                    mma_bf16(acc[mf][nf], ah[mf], bl[nf]);
                    mma_bf16(acc[mf][nf], al[mf], bh[nf]);
                }
        }
    }

    // epilogue: c-frag mapping: e0:(m+0,n+0) e1:(m+0,n+1) e2:(m+8,n+0) e3:(m+8,n+1)
#pragma unroll
    for (int mf = 0; mf < 4; mf++) {
#pragma unroll
        for (int nf = 0; nf < 4; nf++) {
#pragma unroll
            for (int e = 0; e < 4; e++) {
                int m = bm * 128 + wm * 64 + mf * 16 + (lane >> 2) + ((e >> 1) & 1) * 8;
                int n = bn * 128 + wn * 32 + nf * 8 + (lane & 3) * 2 + (e & 1);
                float v = acc[mf][nf][e] + bias[n];
                if (MODE == 0) {
                    int sidx = m >> 2;
                    int bt = m & 3;
                    int h = n / 192;
                    int rr = n - h * 192;
                    int bh2 = bt * HH + h;
                    if (rr < 64)       g_q[((size_t)bh2 * SS + sidx) * DD + rr] = v * 0.125f;
                    else if (rr < 128) g_k[((size_t)bh2 * SS + sidx) * DD + (rr - 64)] = v;
                    else               g_v[((size_t)bh2 * SS + sidx) * DD + (rr - 128)] = v;
                } else {
                    Cout[(size_t)m * 1024 + n] = v;
                }
            }
        }
    }
}

// ---------------------------------------------------------------------------
// Flash attention (proven in rounds 2/3): softmax_1, bias, int32 kpm, abm.
// ---------------------------------------------------------------------------
__device__ __forceinline__ int sw(int row, int col4) {
    return row * 64 + (((col4 ^ (row >> 2)) & 15) << 2);
}

__global__ __launch_bounds__(256) void attn_kernel(
    const float* __restrict__ attn_bias, const float* __restrict__ attn_mul,
    const int* __restrict__ kpm)
{
    __shared__ float Qt[64 * 64];
    __shared__ float KtPs[64 * 64];
    __shared__ float Vs[64 * 64];

    int qt = blockIdx.x;
    int bh = blockIdx.y;
    int b = bh >> 4;
    int h = bh & 15;
    int tid = threadIdx.x;
    int tx = tid & 15;
    int ty = tid >> 4;

    const float* qbase = g_q + ((size_t)bh * SS + qt * 64) * DD;
    const float* kbase = g_k + (size_t)bh * SS * DD;
    const float* vbase = g_v + (size_t)bh * SS * DD;
    const float* bbase = attn_bias + ((size_t)bh * SS + qt * 64) * SS;
    const float* mbase = attn_mul + ((size_t)bh * SS + qt * 64) * SS;
    const int* kp = kpm + b * SS;

#pragma unroll
    for (int t = 0; t < 4; t++) {
        int idx = tid + t * 256;
        int q = idx >> 4;
        int dg = (idx & 15) << 2;
        float4 v = *(const float4*)(qbase + (size_t)q * DD + dg);
        Qt[sw(dg + 0, q >> 2) + (q & 3)] = v.x;
        Qt[sw(dg + 1, q >> 2) + (q & 3)] = v.y;
        Qt[sw(dg + 2, q >> 2) + (q & 3)] = v.z;
        Qt[sw(dg + 3, q >> 2) + (q & 3)] = v.w;
    }

    float acc[4][4];
#pragma unroll
    for (int i = 0; i < 4; i++)
#pragma unroll
        for (int j = 0; j < 4; j++) acc[i][j] = 0.f;
    float mrow[4] = {0.f, 0.f, 0.f, 0.f};
    float lrow[4] = {1.f, 1.f, 1.f, 1.f};

    for (int kt = 0; kt < 16; kt++) {
        int k0 = kt * 64;
        __syncthreads();

#pragma unroll
        for (int t = 0; t < 4; t++) {
            int idx = tid + t * 256;
            int k = idx >> 4;
            int dg = (idx & 15) << 2;
            float4 kv = *(const float4*)(kbase + (size_t)(k0 + k) * DD + dg);
            KtPs[sw(dg + 0, k >> 2) + (k & 3)] = kv.x;
            KtPs[sw(dg + 1, k >> 2) + (k & 3)] = kv.y;
            KtPs[sw(dg + 2, k >> 2) + (k & 3)] = kv.z;
            KtPs[sw(dg + 3, k >> 2) + (k & 3)] = kv.w;
            float4 vv = *(const float4*)(vbase + (size_t)(k0 + k) * DD + dg);
            *(float4*)&Vs[k * 64 + dg] = vv;
        }
        int4 mk = *(const int4*)(kp + k0 + tx * 4);
        __syncthreads();

        float sreg[4][4];
#pragma unroll
        for (int i = 0; i < 4; i++) {
            float4 bv = *(const float4*)(bbase + (size_t)(ty * 4 + i) * SS + k0 + tx * 4);
            sreg[i][0] = bv.x; sreg[i][1] = bv.y; sreg[i][2] = bv.z; sreg[i][3] = bv.w;
        }
#pragma unroll 8
        for (int d = 0; d < 64; d++) {
            float4 a = *(const float4*)&Qt[sw(d, ty)];
            float4 bb2 = *(const float4*)&KtPs[sw(d, tx)];
            sreg[0][0] += a.x * bb2.x; sreg[0][1] += a.x * bb2.y;
            sreg[0][2] += a.x * bb2.z; sreg[0][3] += a.x * bb2.w;
            sreg[1][0] += a.y * bb2.x; sreg[1][1] += a.y * bb2.y;
            sreg[1][2] += a.y * bb2.z; sreg[1][3] += a.y * bb2.w;
            sreg[2][0] += a.z * bb2.x; sreg[2][1] += a.z * bb2.y;
            sreg[2][2] += a.z * bb2.z; sreg[2][3] += a.z * bb2.w;
            sreg[3][0] += a.w * bb2.x; sreg[3][1] += a.w * bb2.y;
            sreg[3][2] += a.w * bb2.z; sreg[3][3] += a.w * bb2.w;
        }
        if (mk.x) { sreg[0][0] = sreg[1][0] = sreg[2][0] = sreg[3][0] = -1e30f; }
        if (mk.y) { sreg[0][1] = sreg[1][1] = sreg[2][1] = sreg[3][1] = -1e30f; }
        if (mk.z) { sreg[0][2] = sreg[1][2] = sreg[2][2] = sreg[3][2] = -1e30f; }
        if (mk.w) { sreg[0][3] = sreg[1][3] = sreg[2][3] = sreg[3][3] = -1e30f; }

#pragma unroll
        for (int i = 0; i < 4; i++) {
            float tm = fmaxf(fmaxf(sreg[i][0], sreg[i][1]), fmaxf(sreg[i][2], sreg[i][3]));
            tm = fmaxf(tm, __shfl_xor_sync(0xffffffffu, tm, 1));
            tm = fmaxf(tm, __shfl_xor_sync(0xffffffffu, tm, 2));
            tm = fmaxf(tm, __shfl_xor_sync(0xffffffffu, tm, 4));
            tm = fmaxf(tm, __shfl_xor_sync(0xffffffffu, tm, 8));
            float mn = fmaxf(mrow[i], tm);
            float sc = __expf(mrow[i] - mn);
            mrow[i] = mn;
            float rs = 0.f;
#pragma unroll
            for (int j = 0; j < 4; j++) {
                float e = __expf(sreg[i][j] - mn);
                sreg[i][j] = e;
                rs += e;
            }
            rs += __shfl_xor_sync(0xffffffffu, rs, 1);
            rs += __shfl_xor_sync(0xffffffffu, rs, 2);
            rs += __shfl_xor_sync(0xffffffffu, rs, 4);
            rs += __shfl_xor_sync(0xffffffffu, rs, 8);
            lrow[i] = lrow[i] * sc + rs;
            acc[i][0] *= sc; acc[i][1] *= sc; acc[i][2] *= sc; acc[i][3] *= sc;
        }

        __syncthreads();

#pragma unroll
        for (int i = 0; i < 4; i++) {
            float4 mv = *(const float4*)(mbase + (size_t)(ty * 4 + i) * SS + k0 + tx * 4);
            sreg[i][0] *= mv.x; sreg[i][1] *= mv.y; sreg[i][2] *= mv.z; sreg[i][3] *= mv.w;
        }
#pragma unroll
        for (int j = 0; j < 4; j++) {
            float4 p4 = make_float4(sreg[0][j], sreg[1][j], sreg[2][j], sreg[3][j]);
            *(float4*)&KtPs[sw(tx * 4 + j, ty)] = p4;
        }
        __syncthreads();

#pragma unroll 8
        for (int kk = 0; kk < 64; kk++) {
            float4 p = *(const float4*)&KtPs[sw(kk, ty)];
            float4 vv = *(const float4*)&Vs[kk * 64 + tx * 4];
            acc[0][0] += p.x * vv.x; acc[0][1] += p.x * vv.y;
            acc[0][2] += p.x * vv.z; acc[0][3] += p.x * vv.w;
            acc[1][0] += p.y * vv.x; acc[1][1] += p.y * vv.y;
            acc[1][2] += p.y * vv.z; acc[1][3] += p.y * vv.w;
            acc[2][0] += p.z * vv.x; acc[2][1] += p.z * vv.y;
            acc[2][2] += p.z * vv.z; acc[2][3] += p.z * vv.w;
            acc[3][0] += p.w * vv.x; acc[3][1] += p.w * vv.y;
            acc[3][2] += p.w * vv.z; acc[3][3] += p.w * vv.w;
        }
    }

#pragma unroll
    for (int i = 0; i < 4; i++) {
        float inv = 1.0f / lrow[i];
        int r = (qt * 64 + ty * 4 + i) * BB + b;
        float4 o = make_float4(acc[i][0] * inv, acc[i][1] * inv,
                               acc[i][2] * inv, acc[i][3] * inv);
        *(float4*)&g_attn[(size_t)r * EE + h * 64 + tx * 4] = o;
    }
}

// ---------------------------------------------------------------------------
extern "C" void kernel_launch(void* const* d_in, const int* in_sizes, int n_in,
                              void* d_out, int out_size)
{
    (void)in_sizes; (void)n_in; (void)out_size;
    const float* x         = (const float*)d_in[0];
    const float* attn_bias = (const float*)d_in[1];
    const float* attn_mul  = (const float*)d_in[2];
    const int*   kpm       = (const int*)d_in[3];
    const float* W_in      = (const float*)d_in[4];
    const float* b_in      = (const float*)d_in[5];
    const float* W_out     = (const float*)d_in[6];
    const float* b_out     = (const float*)d_in[7];
    float* out = (float*)d_out;

    // fp32 -> bf16 hi/lo splits
    split_bf16<<<4096, 256>>>(x,     0, 4096 * 1024 / 4);
    split_bf16<<<3072, 256>>>(W_in,  1, 3072 * 1024 / 4);
    split_bf16<<<1024, 256>>>(W_out, 2, 1024 * 1024 / 4);

    // QKV projection (tensor cores via mma.sync)
    gemm_mma<0><<<dim3(24, 32), 256>>>(b_in, nullptr);

    // attention
    attn_kernel<<<dim3(16, BHH), 256>>>(attn_bias, attn_mul, kpm);

    // attn result split + output projection
    split_bf16<<<4096, 256>>>(nullptr, 3, 4096 * 1024 / 4);
    gemm_mma<1><<<dim3(8, 32), 256>>>(b_out, out);
}

// round 11
// speedup vs baseline: 2.3651x; 1.3642x over previous
#include <cuda_runtime.h>
#include <cuda_bf16.h>
#include <cstdint>

// Problem constants
#define SS 1024
#define BB 4
#define HH 16
#define DD 64
#define EE 1024
#define BHH 64   // B*H

// ---------------------------------------------------------------------------
// Scratch (device globals)
// ---------------------------------------------------------------------------
__device__ __nv_bfloat16 g_qhi[BHH * SS * DD], g_qlo[BHH * SS * DD];
__device__ __nv_bfloat16 g_khi[BHH * SS * DD], g_klo[BHH * SS * DD];
__device__ __nv_bfloat16 g_vhi[BHH * SS * DD], g_vlo[BHH * SS * DD];

__device__ __nv_bfloat16 g_xhi[4096 * 1024], g_xlo[4096 * 1024];
__device__ __nv_bfloat16 g_wihi[3072 * 1024], g_wilo[3072 * 1024];
__device__ __nv_bfloat16 g_wohi[1024 * 1024], g_wolo[1024 * 1024];
__device__ __nv_bfloat16 g_ahi[4096 * 1024], g_alo[4096 * 1024];

// ---------------------------------------------------------------------------
// Warp-level MMA helpers (baseline PTX, works on sm_103 non-'a' target)
// ---------------------------------------------------------------------------
__device__ __forceinline__ uint32_t smem_u32(const void* p) {
    uint32_t a;
    asm("{ .reg .u64 t; cvta.to.shared.u64 t, %1; cvt.u32.u64 %0, t; }"
        : "=r"(a) : "l"(p));
    return a;
}

__device__ __forceinline__ void ldm_x4(uint32_t* r, uint32_t addr) {
    asm volatile("ldmatrix.sync.aligned.m8n8.x4.shared.b16 {%0,%1,%2,%3}, [%4];"
                 : "=r"(r[0]), "=r"(r[1]), "=r"(r[2]), "=r"(r[3]) : "r"(addr));
}
__device__ __forceinline__ void ldm_x2(uint32_t* r, uint32_t addr) {
    asm volatile("ldmatrix.sync.aligned.m8n8.x2.shared.b16 {%0,%1}, [%2];"
                 : "=r"(r[0]), "=r"(r[1]) : "r"(addr));
}
__device__ __forceinline__ void ldm_x2t(uint32_t* r, uint32_t addr) {
    asm volatile("ldmatrix.sync.aligned.m8n8.x2.trans.shared.b16 {%0,%1}, [%2];"
                 : "=r"(r[0]), "=r"(r[1]) : "r"(addr));
}

// D(f32) += A(bf16) @ B(bf16), m16n8k16
__device__ __forceinline__ void mma_bf16(float* c, const uint32_t* a, const uint32_t* b) {
    asm volatile(
        "mma.sync.aligned.m16n8k16.row.col.f32.bf16.bf16.f32 "
        "{%0,%1,%2,%3}, {%4,%5,%6,%7}, {%8,%9}, {%0,%1,%2,%3};"
        : "+f"(c[0]), "+f"(c[1]), "+f"(c[2]), "+f"(c[3])
        : "r"(a[0]), "r"(a[1]), "r"(a[2]), "r"(a[3]), "r"(b[0]), "r"(b[1]));
}

// pack two fp32 -> bf16x2 (x0 in low half, x1 in high half)
__device__ __forceinline__ uint32_t pack2(float x0, float x1) {
    uint32_t r;
    asm("cvt.rn.bf16x2.f32 %0, %1, %2;" : "=r"(r) : "f"(x1), "f"(x0));
    return r;
}
// split pair into hi/lo bf16x2
__device__ __forceinline__ void split2(float x0, float x1, uint32_t& hi, uint32_t& lo) {
    uint32_t hv = pack2(x0, x1);
    float h0 = __uint_as_float(hv << 16);
    float h1 = __uint_as_float(hv & 0xFFFF0000u);
    hi = hv;
    lo = pack2(x0 - h0, x1 - h1);
}

// ---------------------------------------------------------------------------
// fp32 -> bf16 hi/lo split conversion (sel: 0=x, 1=W_in, 2=W_out)
// ---------------------------------------------------------------------------
__global__ __launch_bounds__(256) void split_bf16(const float* __restrict__ in,
                                                  int sel, int n4) {
    int i = blockIdx.x * blockDim.x + threadIdx.x;
    if (i >= n4) return;
    __nv_bfloat16 *hi, *lo;
    if (sel == 0)      { hi = g_xhi;  lo = g_xlo;  }
    else if (sel == 1) { hi = g_wihi; lo = g_wilo; }
    else               { hi = g_wohi; lo = g_wolo; }

    float4 v = ((const float4*)in)[i];
    uint32_t h0, l0, h1, l1;
    split2(v.x, v.y, h0, l0);
    split2(v.z, v.w, h1, l1);
    ((uint2*)hi)[i] = make_uint2(h0, h1);
    ((uint2*)lo)[i] = make_uint2(l0, l1);
}

// ---------------------------------------------------------------------------
// mma.sync split-bf16 GEMM: C[m][n] = sum_k A[m][k]*W[n][k] (+bias)
// MODE 0: A=x(split), W=W_in(split) -> scatter bf16 hi/lo into g_q/k/v (q*0.125)
// MODE 1: A=attn(split), W=W_out(split) -> write d_out (fp32)
// ---------------------------------------------------------------------------
template <int MODE>
__global__ __launch_bounds__(256) void gemm_mma(
    const float* __restrict__ bias, float* __restrict__ Cout)
{
    __shared__ __align__(16) uint4 sAhi[640], sAlo[640], sBhi[640], sBlo[640];

    const __nv_bfloat16* Ahi = (MODE == 0) ? g_xhi  : g_ahi;
    const __nv_bfloat16* Alo = (MODE == 0) ? g_xlo  : g_alo;
    const __nv_bfloat16* Bhi = (MODE == 0) ? g_wihi : g_wohi;
    const __nv_bfloat16* Blo = (MODE == 0) ? g_wilo : g_wolo;

    const int tid = threadIdx.x;
    const int lane = tid & 31;
    const int wid = tid >> 5;
    const int wm = wid >> 2;
    const int wn = wid & 3;
    const int bm = blockIdx.y, bn = blockIdx.x;
    const int K = 1024;

    float acc[4][4][4];
#pragma unroll
    for (int mf = 0; mf < 4; mf++)
#pragma unroll
        for (int nf = 0; nf < 4; nf++)
#pragma unroll
            for (int e = 0; e < 4; e++) acc[mf][nf][e] = 0.f;

    const uint32_t uAhi = smem_u32(sAhi), uAlo = smem_u32(sAlo);
    const uint32_t uBhi = smem_u32(sBhi), uBlo = smem_u32(sBlo);

    const int a_row = wm * 64 + (lane & 7) + ((lane >> 3) & 1) * 8;
    const int a_kc  = (lane >> 4) & 1;
    const int b_row = wn * 32 + (lane & 7);
    const int b_kc  = (lane >> 3) & 1;

    for (int kt = 0; kt < 32; kt++) {
        const int k0 = kt * 32;
        uint4 va[2], vb[2], vc[2], vd[2];
#pragma unroll
        for (int q = 0; q < 2; q++) {
            int c = tid + q * 256;
            int row = c >> 2, kc = c & 3;
            size_t ao = (size_t)(bm * 128 + row) * K + k0 + kc * 8;
            size_t bo = (size_t)(bn * 128 + row) * K + k0 + kc * 8;
            va[q] = *(const uint4*)(Ahi + ao);
            vb[q] = *(const uint4*)(Alo + ao);
            vc[q] = *(const uint4*)(Bhi + bo);
            vd[q] = *(const uint4*)(Blo + bo);
        }
        __syncthreads();
#pragma unroll
        for (int q = 0; q < 2; q++) {
            int c = tid + q * 256;
            int row = c >> 2, kc = c & 3;
            int p = row * 5 + kc;
            sAhi[p] = va[q]; sAlo[p] = vb[q];
            sBhi[p] = vc[q]; sBlo[p] = vd[q];
        }
        __syncthreads();

#pragma unroll
        for (int ks = 0; ks < 2; ks++) {
            uint32_t ah[4][4], al[4][4], bh[4][2], bl[4][2];
#pragma unroll
            for (int mf = 0; mf < 4; mf++) {
                uint32_t off = (uint32_t)(((a_row + mf * 16) * 5 + ks * 2 + a_kc) * 16);
                ldm_x4(ah[mf], uAhi + off);
                ldm_x4(al[mf], uAlo + off);
            }
#pragma unroll
            for (int nf = 0; nf < 4; nf++) {
                uint32_t off = (uint32_t)(((b_row + nf * 8) * 5 + ks * 2 + b_kc) * 16);
                ldm_x2(bh[nf], uBhi + off);
                ldm_x2(bl[nf], uBlo + off);
            }
#pragma unroll
            for (int mf = 0; mf < 4; mf++)
#pragma unroll
                for (int nf = 0; nf < 4; nf++) {
                    mma_bf16(acc[mf][nf], ah[mf], bh[nf]);
                    mma_bf16(acc[mf][nf], ah[mf], bl[nf]);
                    mma_bf16(acc[mf][nf], al[mf], bh[nf]);
                }
        }
    }

#pragma unroll
    for (int mf = 0; mf < 4; mf++) {
#pragma unroll
        for (int nf = 0; nf < 4; nf++) {
#pragma unroll
            for (int e = 0; e < 4; e++) {
                int m = bm * 128 + wm * 64 + mf * 16 + (lane >> 2) + ((e >> 1) & 1) * 8;
                int n = bn * 128 + wn * 32 + nf * 8 + (lane & 3) * 2 + (e & 1);
                float v = acc[mf][nf][e] + bias[n];
                if (MODE == 0) {
                    int sidx = m >> 2;
                    int bt = m & 3;
                    int h = n / 192;
                    int rr = n - h * 192;
                    int bh2 = bt * HH + h;
                    __nv_bfloat16 *dh, *dl;
                    int dcol;
                    if (rr < 64)       { dh = g_qhi; dl = g_qlo; dcol = rr;       v *= 0.125f; }
                    else if (rr < 128) { dh = g_khi; dl = g_klo; dcol = rr - 64;  }
                    else               { dh = g_vhi; dl = g_vlo; dcol = rr - 128; }
                    size_t idx = ((size_t)bh2 * SS + sidx) * DD + dcol;
                    __nv_bfloat16 hv = __float2bfloat16(v);
                    __nv_bfloat16 lv = __float2bfloat16(v - __bfloat162float(hv));
                    dh[idx] = hv;
                    dl[idx] = lv;
                } else {
                    Cout[(size_t)m * 1024 + n] = v;
                }
            }
        }
    }
}

// ---------------------------------------------------------------------------
// Flash attention on mma.sync: softmax_1 (phantom logit -> m=0, l=1), bias,
// mask folded into staged bias/mul, 3-term split-bf16 for QK^T and PV.
// Block: 128 threads (4 warps x 16 q rows). Grid: (16 q-tiles, 64 bh).
// Dynamic smem (67584 B):
//   [0)       Khi 8KB   [8192) Klo 8KB  [16384) Vhi 8KB  [24576) Vlo 8KB
//   [32768)   bias fp32 64x68 (17408 B)   (Q hi/lo staged here pre-loop)
//   [50176)   mul  fp32 64x68 (17408 B)
// ---------------------------------------------------------------------------
#define TSWZ(row, ch) ((((row)) << 7) + ((((ch) ^ ((row) & 7))) << 4))
#define SBP 68

__global__ __launch_bounds__(128) void attn_mma(
    const float* __restrict__ bias_g, const float* __restrict__ mul_g,
    const int* __restrict__ kpm)
{
    extern __shared__ uint8_t sm[];
    float* sB = (float*)(sm + 32768);
    float* sM = (float*)(sm + 50176);

    const int tid = threadIdx.x;
    const int lane = tid & 31;
    const int warp = tid >> 5;
    const int qt = blockIdx.x, bh = blockIdx.y;
    const int b = bh >> 4, h = bh & 15;
    const uint32_t uSm = smem_u32(sm);

    const __nv_bfloat16* qhi = g_qhi + ((size_t)bh * SS + qt * 64) * DD;
    const __nv_bfloat16* qlo = g_qlo + ((size_t)bh * SS + qt * 64) * DD;
    const __nv_bfloat16* khi = g_khi + (size_t)bh * SS * DD;
    const __nv_bfloat16* klo = g_klo + (size_t)bh * SS * DD;
    const __nv_bfloat16* vhi = g_vhi + (size_t)bh * SS * DD;
    const __nv_bfloat16* vlo = g_vlo + (size_t)bh * SS * DD;
    const float* bbase = bias_g + ((size_t)bh * SS + qt * 64) * SS;
    const float* mbase = mul_g + ((size_t)bh * SS + qt * 64) * SS;
    const int* kp = kpm + b * SS;

    // ---- stage Q into smem (at sB region), load A-fragments, then free it
#pragma unroll
    for (int t = 0; t < 4; t++) {
        int idx = tid + t * 128;
        int row = idx >> 3, ch = idx & 7;
        *(uint4*)(sm + 32768 + TSWZ(row, ch)) = *(const uint4*)(qhi + row * 64 + ch * 8);
        *(uint4*)(sm + 40960 + TSWZ(row, ch)) = *(const uint4*)(qlo + row * 64 + ch * 8);
    }
    __syncthreads();

    uint32_t qh[4][4], ql[4][4];
    {
        int arow = warp * 16 + (lane & 7) + ((lane >> 3) & 1) * 8;
        int akc = (lane >> 4) & 1;
#pragma unroll
        for (int ds = 0; ds < 4; ds++) {
            uint32_t off = (uint32_t)TSWZ(arow, ds * 2 + akc);
            ldm_x4(qh[ds], uSm + 32768 + off);
            ldm_x4(ql[ds], uSm + 40960 + off);
        }
    }

    float acc[8][4];
#pragma unroll
    for (int i = 0; i < 8; i++)
#pragma unroll
        for (int e = 0; e < 4; e++) acc[i][e] = 0.f;
    float m0 = 0.f, m1 = 0.f, l0 = 1.f, l1 = 1.f;   // phantom logit 0

    const int r0 = warp * 16 + (lane >> 2);   // q row in tile (and r0+8)
    const int cc = (lane & 3) * 2;
    const int brow = lane & 7;
    const int bkc = (lane >> 3) & 1;
    const int vrow = (lane & 7) + ((lane >> 3) & 1) * 8;

    for (int kt = 0; kt < 16; kt++) {
        const int k0 = kt * 64;
        __syncthreads();   // all warps done with previous tiles (and Q frags)

        // stage K/V hi/lo (swizzled)
#pragma unroll
        for (int t = 0; t < 4; t++) {
            int idx = tid + t * 128;
            int row = idx >> 3, ch = idx & 7;
            size_t go = (size_t)(k0 + row) * 64 + ch * 8;
            uint32_t so = TSWZ(row, ch);
            *(uint4*)(sm + so)         = *(const uint4*)(khi + go);
            *(uint4*)(sm + 8192 + so)  = *(const uint4*)(klo + go);
            *(uint4*)(sm + 16384 + so) = *(const uint4*)(vhi + go);
            *(uint4*)(sm + 24576 + so) = *(const uint4*)(vlo + go);
        }
        // stage bias/mul with mask folded in
#pragma unroll
        for (int t = 0; t < 8; t++) {
            int idx = tid + t * 128;
            int row = idx >> 4, c4 = idx & 15;
            int col = c4 * 4;
            int4 mk = *(const int4*)(kp + k0 + col);
            float4 bv = *(const float4*)(bbase + (size_t)row * SS + k0 + col);
            float4 mv = *(const float4*)(mbase + (size_t)row * SS + k0 + col);
            if (mk.x) { bv.x = -1e30f; mv.x = 0.f; }
            if (mk.y) { bv.y = -1e30f; mv.y = 0.f; }
            if (mk.z) { bv.z = -1e30f; mv.z = 0.f; }
            if (mk.w) { bv.w = -1e30f; mv.w = 0.f; }
            *(float4*)&sB[row * SBP + col] = bv;
            *(float4*)&sM[row * SBP + col] = mv;
        }
        __syncthreads();

        // ---- S = bias + Q K^T (3-term)
        float s[8][4];
#pragma unroll
        for (int nf = 0; nf < 8; nf++) {
            float2 t0 = *(float2*)&sB[r0 * SBP + nf * 8 + cc];
            float2 t1 = *(float2*)&sB[(r0 + 8) * SBP + nf * 8 + cc];
            s[nf][0] = t0.x; s[nf][1] = t0.y; s[nf][2] = t1.x; s[nf][3] = t1.y;
        }
#pragma unroll
        for (int ds = 0; ds < 4; ds++) {
#pragma unroll
            for (int nf = 0; nf < 8; nf++) {
                uint32_t kh2[2], kl2[2];
                uint32_t off = (uint32_t)TSWZ(nf * 8 + brow, ds * 2 + bkc);
                ldm_x2(kh2, uSm + off);
                ldm_x2(kl2, uSm + 8192 + off);
                mma_bf16(s[nf], qh[ds], kh2);
                mma_bf16(s[nf], qh[ds], kl2);
                mma_bf16(s[nf], ql[ds], kh2);
            }
        }

        // ---- online softmax_1 (rows r0 and r0+8)
        float tm0 = s[0][0], tm1 = s[0][2];
#pragma unroll
        for (int nf = 0; nf < 8; nf++) {
            tm0 = fmaxf(tm0, fmaxf(s[nf][0], s[nf][1]));
            tm1 = fmaxf(tm1, fmaxf(s[nf][2], s[nf][3]));
        }
        tm0 = fmaxf(tm0, __shfl_xor_sync(0xffffffffu, tm0, 1));
        tm0 = fmaxf(tm0, __shfl_xor_sync(0xffffffffu, tm0, 2));
        tm1 = fmaxf(tm1, __shfl_xor_sync(0xffffffffu, tm1, 1));
        tm1 = fmaxf(tm1, __shfl_xor_sync(0xffffffffu, tm1, 2));
        float mn0 = fmaxf(m0, tm0), mn1 = fmaxf(m1, tm1);
        float sc0 = __expf(m0 - mn0), sc1 = __expf(m1 - mn1);
        m0 = mn0; m1 = mn1;
        float rs0 = 0.f, rs1 = 0.f;
#pragma unroll
        for (int nf = 0; nf < 8; nf++) {
            s[nf][0] = __expf(s[nf][0] - mn0);
            s[nf][1] = __expf(s[nf][1] - mn0);
            s[nf][2] = __expf(s[nf][2] - mn1);
            s[nf][3] = __expf(s[nf][3] - mn1);
            rs0 += s[nf][0] + s[nf][1];
            rs1 += s[nf][2] + s[nf][3];
        }
        rs0 += __shfl_xor_sync(0xffffffffu, rs0, 1);
        rs0 += __shfl_xor_sync(0xffffffffu, rs0, 2);
        rs1 += __shfl_xor_sync(0xffffffffu, rs1, 1);
        rs1 += __shfl_xor_sync(0xffffffffu, rs1, 2);
        l0 = l0 * sc0 + rs0;
        l1 = l1 * sc1 + rs1;
#pragma unroll
        for (int i = 0; i < 8; i++) {
            acc[i][0] *= sc0; acc[i][1] *= sc0;
            acc[i][2] *= sc1; acc[i][3] *= sc1;
        }

        // ---- p *= abm
#pragma unroll
        for (int nf = 0; nf < 8; nf++) {
            float2 t0 = *(float2*)&sM[r0 * SBP + nf * 8 + cc];
            float2 t1 = *(float2*)&sM[(r0 + 8) * SBP + nf * 8 + cc];
            s[nf][0] *= t0.x; s[nf][1] *= t0.y; s[nf][2] *= t1.x; s[nf][3] *= t1.y;
        }

        // ---- acc += P V (3-term; P repacked from C frags, V via ldmatrix.trans)
#pragma unroll
        for (int ks = 0; ks < 4; ks++) {
            uint32_t ahi[4], alo[4];
            split2(s[2 * ks][0],     s[2 * ks][1],     ahi[0], alo[0]);
            split2(s[2 * ks][2],     s[2 * ks][3],     ahi[1], alo[1]);
            split2(s[2 * ks + 1][0], s[2 * ks + 1][1], ahi[2], alo[2]);
            split2(s[2 * ks + 1][2], s[2 * ks + 1][3], ahi[3], alo[3]);
#pragma unroll
            for (int nfd = 0; nfd < 8; nfd++) {
                uint32_t vh2[2], vl2[2];
                uint32_t off = (uint32_t)TSWZ(ks * 16 + vrow, nfd);
                ldm_x2t(vh2, uSm + 16384 + off);
                ldm_x2t(vl2, uSm + 24576 + off);
                mma_bf16(acc[nfd], ahi, vh2);
                mma_bf16(acc[nfd], ahi, vl2);
                mma_bf16(acc[nfd], alo, vh2);
            }
        }
    }

    // ---- epilogue: out = acc / l, write bf16 hi/lo splits for out-projection
    float inv0 = 1.0f / l0, inv1 = 1.0f / l1;
    int q0 = qt * 64 + r0;
    size_t o0 = ((size_t)q0 * BB + b) * EE + h * 64;
    size_t o1 = ((size_t)(q0 + 8) * BB + b) * EE + h * 64;
#pragma unroll
    for (int nfd = 0; nfd < 8; nfd++) {
        int dc = nfd * 8 + cc;
        uint32_t h0, lo0, h1, lo1;
        split2(acc[nfd][0] * inv0, acc[nfd][1] * inv0, h0, lo0);
        split2(acc[nfd][2] * inv1, acc[nfd][3] * inv1, h1, lo1);
        *(uint32_t*)(g_ahi + o0 + dc) = h0;
        *(uint32_t*)(g_alo + o0 + dc) = lo0;
        *(uint32_t*)(g_ahi + o1 + dc) = h1;
        *(uint32_t*)(g_alo + o1 + dc) = lo1;
    }
}

// ---------------------------------------------------------------------------
extern "C" void kernel_launch(void* const* d_in, const int* in_sizes, int n_in,
                              void* d_out, int out_size)
{
    (void)in_sizes; (void)n_in; (void)out_size;
    const float* x         = (const float*)d_in[0];
    const float* attn_bias = (const float*)d_in[1];
    const float* attn_mul  = (const float*)d_in[2];
    const int*   kpm       = (const int*)d_in[3];
    const float* W_in      = (const float*)d_in[4];
    const float* b_in      = (const float*)d_in[5];
    const float* W_out     = (const float*)d_in[6];
    const float* b_out     = (const float*)d_in[7];
    float* out = (float*)d_out;

    const int ATTN_SMEM = 67584;
    cudaFuncSetAttribute(attn_mma, cudaFuncAttributeMaxDynamicSharedMemorySize, ATTN_SMEM);

    // fp32 -> bf16 hi/lo splits
    split_bf16<<<4096, 256>>>(x,     0, 4096 * 1024 / 4);
    split_bf16<<<3072, 256>>>(W_in,  1, 3072 * 1024 / 4);
    split_bf16<<<1024, 256>>>(W_out, 2, 1024 * 1024 / 4);

    // QKV projection (tensor cores, writes bf16 hi/lo q/k/v)
    gemm_mma<0><<<dim3(24, 32), 256>>>(b_in, nullptr);

    // attention (tensor cores, writes bf16 hi/lo attn result)
    attn_mma<<<dim3(16, BHH), 128, ATTN_SMEM>>>(attn_bias, attn_mul, kpm);

    // output projection
    gemm_mma<1><<<dim3(8, 32), 256>>>(b_out, out);
}

// round 12
// speedup vs baseline: 2.4402x; 1.0318x over previous
#include <cuda_runtime.h>
#include <cuda_bf16.h>
#include <cstdint>

// Problem constants
#define SS 1024
#define BB 4
#define HH 16
#define DD 64
#define EE 1024
#define BHH 64   // B*H

// ---------------------------------------------------------------------------
// Scratch (device globals)
// ---------------------------------------------------------------------------
__device__ __nv_bfloat16 g_qhi[BHH * SS * DD], g_qlo[BHH * SS * DD];
__device__ __nv_bfloat16 g_khi[BHH * SS * DD], g_klo[BHH * SS * DD];
__device__ __nv_bfloat16 g_vhi[BHH * SS * DD], g_vlo[BHH * SS * DD];

__device__ __nv_bfloat16 g_xhi[4096 * 1024], g_xlo[4096 * 1024];
__device__ __nv_bfloat16 g_wihi[3072 * 1024], g_wilo[3072 * 1024];
__device__ __nv_bfloat16 g_wohi[1024 * 1024], g_wolo[1024 * 1024];
__device__ __nv_bfloat16 g_ahi[4096 * 1024], g_alo[4096 * 1024];

// ---------------------------------------------------------------------------
// Warp-level MMA helpers (baseline PTX, works on sm_103 non-'a' target)
// ---------------------------------------------------------------------------
__device__ __forceinline__ uint32_t smem_u32(const void* p) {
    uint32_t a;
    asm("{ .reg .u64 t; cvta.to.shared.u64 t, %1; cvt.u32.u64 %0, t; }"
        : "=r"(a) : "l"(p));
    return a;
}

__device__ __forceinline__ void ldm_x4(uint32_t* r, uint32_t addr) {
    asm volatile("ldmatrix.sync.aligned.m8n8.x4.shared.b16 {%0,%1,%2,%3}, [%4];"
                 : "=r"(r[0]), "=r"(r[1]), "=r"(r[2]), "=r"(r[3]) : "r"(addr));
}
__device__ __forceinline__ void ldm_x2(uint32_t* r, uint32_t addr) {
    asm volatile("ldmatrix.sync.aligned.m8n8.x2.shared.b16 {%0,%1}, [%2];"
                 : "=r"(r[0]), "=r"(r[1]) : "r"(addr));
}
__device__ __forceinline__ void ldm_x2t(uint32_t* r, uint32_t addr) {
    asm volatile("ldmatrix.sync.aligned.m8n8.x2.trans.shared.b16 {%0,%1}, [%2];"
                 : "=r"(r[0]), "=r"(r[1]) : "r"(addr));
}

// D(f32) += A(bf16) @ B(bf16), m16n8k16
__device__ __forceinline__ void mma_bf16(float* c, const uint32_t* a, const uint32_t* b) {
    asm volatile(
        "mma.sync.aligned.m16n8k16.row.col.f32.bf16.bf16.f32 "
        "{%0,%1,%2,%3}, {%4,%5,%6,%7}, {%8,%9}, {%0,%1,%2,%3};"
        : "+f"(c[0]), "+f"(c[1]), "+f"(c[2]), "+f"(c[3])
        : "r"(a[0]), "r"(a[1]), "r"(a[2]), "r"(a[3]), "r"(b[0]), "r"(b[1]));
}

// cp.async 16B
__device__ __forceinline__ void cp16(uint32_t dst, const void* src) {
    asm volatile("cp.async.cg.shared.global [%0], [%1], 16;" :: "r"(dst), "l"(src));
}
#define CP_COMMIT() asm volatile("cp.async.commit_group;" ::: "memory")
#define CP_WAIT(N)  asm volatile("cp.async.wait_group %0;" :: "n"(N) : "memory")

// pack two fp32 -> bf16x2 (x0 in low half, x1 in high half)
__device__ __forceinline__ uint32_t pack2(float x0, float x1) {
    uint32_t r;
    asm("cvt.rn.bf16x2.f32 %0, %1, %2;" : "=r"(r) : "f"(x1), "f"(x0));
    return r;
}
// split pair into hi/lo bf16x2
__device__ __forceinline__ void split2(float x0, float x1, uint32_t& hi, uint32_t& lo) {
    uint32_t hv = pack2(x0, x1);
    float h0 = __uint_as_float(hv << 16);
    float h1 = __uint_as_float(hv & 0xFFFF0000u);
    hi = hv;
    lo = pack2(x0 - h0, x1 - h1);
}

// ---------------------------------------------------------------------------
// fp32 -> bf16 hi/lo splits for x, W_in, W_out in ONE launch.
// blocks [0,4096): x | [4096,7168): W_in | [7168,8192): W_out
// ---------------------------------------------------------------------------
__global__ __launch_bounds__(256) void split_all(const float* __restrict__ x,
                                                 const float* __restrict__ wi,
                                                 const float* __restrict__ wo) {
    int bid = blockIdx.x;
    const float* src;
    __nv_bfloat16 *hi, *lo;
    int i;
    if (bid < 4096)      { src = x;  hi = g_xhi;  lo = g_xlo;  i = bid * 256 + threadIdx.x; }
    else if (bid < 7168) { src = wi; hi = g_wihi; lo = g_wilo; i = (bid - 4096) * 256 + threadIdx.x; }
    else                 { src = wo; hi = g_wohi; lo = g_wolo; i = (bid - 7168) * 256 + threadIdx.x; }

    float4 v = ((const float4*)src)[i];
    uint32_t h0, l0, h1, l1;
    split2(v.x, v.y, h0, l0);
    split2(v.z, v.w, h1, l1);
    ((uint2*)hi)[i] = make_uint2(h0, h1);
    ((uint2*)lo)[i] = make_uint2(l0, l1);
}

// ---------------------------------------------------------------------------
// mma.sync split-bf16 GEMM, cp.async double-buffered:
//   C[m][n] = sum_k A[m][k]*W[n][k] (+bias);  C ~= AhiWhi + AhiWlo + AloWhi
// CTA 128x128, K-tile 32, 8 warps (2x4), warp tile 64x32.
// Dynamic smem: 2 buffers x 4 arrays x 640 uint4 (pitch-5 rows) = 81920 B.
// MODE 0: A=x(split), W=W_in(split) -> scatter bf16 hi/lo q/k/v (q*0.125)
// MODE 1: A=attn(split), W=W_out(split) -> write d_out (fp32)
// ---------------------------------------------------------------------------
#define BUF_U4 2560          // uint4 per buffer (4 arrays x 640)
#define ARR_U4 640

template <int MODE>
__global__ __launch_bounds__(256) void gemm_mma(
    const float* __restrict__ bias, float* __restrict__ Cout)
{
    extern __shared__ __align__(16) uint4 smem[];

    const __nv_bfloat16* Ahi = (MODE == 0) ? g_xhi  : g_ahi;
    const __nv_bfloat16* Alo = (MODE == 0) ? g_xlo  : g_alo;
    const __nv_bfloat16* Bhi = (MODE == 0) ? g_wihi : g_wohi;
    const __nv_bfloat16* Blo = (MODE == 0) ? g_wilo : g_wolo;

    const int tid = threadIdx.x;
    const int lane = tid & 31;
    const int wid = tid >> 5;
    const int wm = wid >> 2;
    const int wn = wid & 3;
    const int bm = blockIdx.y, bn = blockIdx.x;
    const int K = 1024;

    float acc[4][4][4];
#pragma unroll
    for (int mf = 0; mf < 4; mf++)
#pragma unroll
        for (int nf = 0; nf < 4; nf++)
#pragma unroll
            for (int e = 0; e < 4; e++) acc[mf][nf][e] = 0.f;

    const uint32_t uS = smem_u32(smem);

    // per-thread cp.async source/dest precompute: 8 chunks
    //   q in 0..7: array a = q>>1 (0:Ahi 1:Alo 2:Bhi 3:Blo), sub = (q&1)*256+tid
    const __nv_bfloat16* gsrc[4] = {Ahi, Alo, Bhi, Blo};

    // issue one K-tile's loads into buffer b
    auto issue = [&](int kt, int b) {
        const int k0 = kt * 32;
#pragma unroll
        for (int q = 0; q < 8; q++) {
            int a = q >> 1;
            int sub = (q & 1) * 256 + tid;
            int row = sub >> 2, kc = sub & 3;
            int gr = (a < 2 ? bm : bn) * 128 + row;
            const __nv_bfloat16* src = gsrc[a] + (size_t)gr * K + k0 + kc * 8;
            uint32_t dst = uS + (uint32_t)(b * BUF_U4 + a * ARR_U4 + row * 5 + kc) * 16u;
            cp16(dst, src);
        }
        CP_COMMIT();
    };

    const int a_row = wm * 64 + (lane & 7) + ((lane >> 3) & 1) * 8;
    const int a_kc  = (lane >> 4) & 1;
    const int b_row = wn * 32 + (lane & 7);
    const int b_kc  = (lane >> 3) & 1;

    issue(0, 0);

    for (int kt = 0; kt < 32; kt++) {
        const int b = kt & 1;
        if (kt < 31) issue(kt + 1, b ^ 1);
        if (kt < 31) { CP_WAIT(1); } else { CP_WAIT(0); }
        __syncthreads();

        const uint32_t uAhi = uS + (uint32_t)(b * BUF_U4) * 16u;
        const uint32_t uAlo = uAhi + ARR_U4 * 16u;
        const uint32_t uBhi = uAlo + ARR_U4 * 16u;
        const uint32_t uBlo = uBhi + ARR_U4 * 16u;

#pragma unroll
        for (int ks = 0; ks < 2; ks++) {
            uint32_t ah[4][4], al[4][4], bh[4][2], bl[4][2];
#pragma unroll
            for (int mf = 0; mf < 4; mf++) {
                uint32_t off = (uint32_t)(((a_row + mf * 16) * 5 + ks * 2 + a_kc) * 16);
                ldm_x4(ah[mf], uAhi + off);
                ldm_x4(al[mf], uAlo + off);
            }
#pragma unroll
            for (int nf = 0; nf < 4; nf++) {
                uint32_t off = (uint32_t)(((b_row + nf * 8) * 5 + ks * 2 + b_kc) * 16);
                ldm_x2(bh[nf], uBhi + off);
                ldm_x2(bl[nf], uBlo + off);
            }
#pragma unroll
            for (int mf = 0; mf < 4; mf++)
#pragma unroll
                for (int nf = 0; nf < 4; nf++) {
                    mma_bf16(acc[mf][nf], ah[mf], bh[nf]);
                    mma_bf16(acc[mf][nf], ah[mf], bl[nf]);
                    mma_bf16(acc[mf][nf], al[mf], bh[nf]);
                }
        }
        __syncthreads();   // protect buffer b before kt+2 overwrites it
    }

#pragma unroll
    for (int mf = 0; mf < 4; mf++) {
#pragma unroll
        for (int nf = 0; nf < 4; nf++) {
#pragma unroll
            for (int e = 0; e < 4; e++) {
                int m = bm * 128 + wm * 64 + mf * 16 + (lane >> 2) + ((e >> 1) & 1) * 8;
                int n = bn * 128 + wn * 32 + nf * 8 + (lane & 3) * 2 + (e & 1);
                float v = acc[mf][nf][e] + bias[n];
                if (MODE == 0) {
                    int sidx = m >> 2;
                    int bt = m & 3;
                    int h = n / 192;
                    int rr = n - h * 192;
                    int bh2 = bt * HH + h;
                    __nv_bfloat16 *dh, *dl;
                    int dcol;
                    if (rr < 64)       { dh = g_qhi; dl = g_qlo; dcol = rr;       v *= 0.125f; }
                    else if (rr < 128) { dh = g_khi; dl = g_klo; dcol = rr - 64;  }
                    else               { dh = g_vhi; dl = g_vlo; dcol = rr - 128; }
                    size_t idx = ((size_t)bh2 * SS + sidx) * DD + dcol;
                    __nv_bfloat16 hv = __float2bfloat16(v);
                    __nv_bfloat16 lv = __float2bfloat16(v - __bfloat162float(hv));
                    dh[idx] = hv;
                    dl[idx] = lv;
                } else {
                    Cout[(size_t)m * 1024 + n] = v;
                }
            }
        }
    }
}

// ---------------------------------------------------------------------------
// Flash attention on mma.sync (unchanged from round 6/11 passing version)
// ---------------------------------------------------------------------------
#define TSWZ(row, ch) ((((row)) << 7) + ((((ch) ^ ((row) & 7))) << 4))
#define SBP 68

__global__ __launch_bounds__(128) void attn_mma(
    const float* __restrict__ bias_g, const float* __restrict__ mul_g,
    const int* __restrict__ kpm)
{
    extern __shared__ uint8_t sm[];
    float* sB = (float*)(sm + 32768);
    float* sM = (float*)(sm + 50176);

    const int tid = threadIdx.x;
    const int lane = tid & 31;
    const int warp = tid >> 5;
    const int qt = blockIdx.x, bh = blockIdx.y;
    const int b = bh >> 4, h = bh & 15;
    const uint32_t uSm = smem_u32(sm);

    const __nv_bfloat16* qhi = g_qhi + ((size_t)bh * SS + qt * 64) * DD;
    const __nv_bfloat16* qlo = g_qlo + ((size_t)bh * SS + qt * 64) * DD;
    const __nv_bfloat16* khi = g_khi + (size_t)bh * SS * DD;
    const __nv_bfloat16* klo = g_klo + (size_t)bh * SS * DD;
    const __nv_bfloat16* vhi = g_vhi + (size_t)bh * SS * DD;
    const __nv_bfloat16* vlo = g_vlo + (size_t)bh * SS * DD;
    const float* bbase = bias_g + ((size_t)bh * SS + qt * 64) * SS;
    const float* mbase = mul_g + ((size_t)bh * SS + qt * 64) * SS;
    const int* kp = kpm + b * SS;

    // ---- stage Q into smem (at sB region), load A-fragments, then free it
#pragma unroll
    for (int t = 0; t < 4; t++) {
        int idx = tid + t * 128;
        int row = idx >> 3, ch = idx & 7;
        *(uint4*)(sm + 32768 + TSWZ(row, ch)) = *(const uint4*)(qhi + row * 64 + ch * 8);
        *(uint4*)(sm + 40960 + TSWZ(row, ch)) = *(const uint4*)(qlo + row * 64 + ch * 8);
    }
    __syncthreads();

    uint32_t qh[4][4], ql[4][4];
    {
        int arow = warp * 16 + (lane & 7) + ((lane >> 3) & 1) * 8;
        int akc = (lane >> 4) & 1;
#pragma unroll
        for (int ds = 0; ds < 4; ds++) {
            uint32_t off = (uint32_t)TSWZ(arow, ds * 2 + akc);
            ldm_x4(qh[ds], uSm + 32768 + off);
            ldm_x4(ql[ds], uSm + 40960 + off);
        }
    }

    float acc[8][4];
#pragma unroll
    for (int i = 0; i < 8; i++)
#pragma unroll
        for (int e = 0; e < 4; e++) acc[i][e] = 0.f;
    float m0 = 0.f, m1 = 0.f, l0 = 1.f, l1 = 1.f;   // phantom logit 0

    const int r0 = warp * 16 + (lane >> 2);
    const int cc = (lane & 3) * 2;
    const int brow = lane & 7;
    const int bkc = (lane >> 3) & 1;
    const int vrow = (lane & 7) + ((lane >> 3) & 1) * 8;

    for (int kt = 0; kt < 16; kt++) {
        const int k0 = kt * 64;
        __syncthreads();

#pragma unroll
        for (int t = 0; t < 4; t++) {
            int idx = tid + t * 128;
            int row = idx >> 3, ch = idx & 7;
            size_t go = (size_t)(k0 + row) * 64 + ch * 8;
            uint32_t so = TSWZ(row, ch);
            *(uint4*)(sm + so)         = *(const uint4*)(khi + go);
            *(uint4*)(sm + 8192 + so)  = *(const uint4*)(klo + go);
            *(uint4*)(sm + 16384 + so) = *(const uint4*)(vhi + go);
            *(uint4*)(sm + 24576 + so) = *(const uint4*)(vlo + go);
        }
#pragma unroll
        for (int t = 0; t < 8; t++) {
            int idx = tid + t * 128;
            int row = idx >> 4, c4 = idx & 15;
            int col = c4 * 4;
            int4 mk = *(const int4*)(kp + k0 + col);
            float4 bv = *(const float4*)(bbase + (size_t)row * SS + k0 + col);
            float4 mv = *(const float4*)(mbase + (size_t)row * SS + k0 + col);
            if (mk.x) { bv.x = -1e30f; mv.x = 0.f; }
            if (mk.y) { bv.y = -1e30f; mv.y = 0.f; }
            if (mk.z) { bv.z = -1e30f; mv.z = 0.f; }
            if (mk.w) { bv.w = -1e30f; mv.w = 0.f; }
            *(float4*)&sB[row * SBP + col] = bv;
            *(float4*)&sM[row * SBP + col] = mv;
        }
        __syncthreads();

        // ---- S = bias + Q K^T (3-term)
        float s[8][4];
#pragma unroll
        for (int nf = 0; nf < 8; nf++) {
            float2 t0 = *(float2*)&sB[r0 * SBP + nf * 8 + cc];
            float2 t1 = *(float2*)&sB[(r0 + 8) * SBP + nf * 8 + cc];
            s[nf][0] = t0.x; s[nf][1] = t0.y; s[nf][2] = t1.x; s[nf][3] = t1.y;
        }
#pragma unroll
        for (int ds = 0; ds < 4; ds++) {
#pragma unroll
            for (int nf = 0; nf < 8; nf++) {
                uint32_t kh2[2], kl2[2];
                uint32_t off = (uint32_t)TSWZ(nf * 8 + brow, ds * 2 + bkc);
                ldm_x2(kh2, uSm + off);
                ldm_x2(kl2, uSm + 8192 + off);
                mma_bf16(s[nf], qh[ds], kh2);
                mma_bf16(s[nf], qh[ds], kl2);
                mma_bf16(s[nf], ql[ds], kh2);
            }
        }

        // ---- online softmax_1
        float tm0 = s[0][0], tm1 = s[0][2];
#pragma unroll
        for (int nf = 0; nf < 8; nf++) {
            tm0 = fmaxf(tm0, fmaxf(s[nf][0], s[nf][1]));
            tm1 = fmaxf(tm1, fmaxf(s[nf][2], s[nf][3]));
        }
        tm0 = fmaxf(tm0, __shfl_xor_sync(0xffffffffu, tm0, 1));
        tm0 = fmaxf(tm0, __shfl_xor_sync(0xffffffffu, tm0, 2));
        tm1 = fmaxf(tm1, __shfl_xor_sync(0xffffffffu, tm1, 1));
        tm1 = fmaxf(tm1, __shfl_xor_sync(0xffffffffu, tm1, 2));
        float mn0 = fmaxf(m0, tm0), mn1 = fmaxf(m1, tm1);
        float sc0 = __expf(m0 - mn0), sc1 = __expf(m1 - mn1);
        m0 = mn0; m1 = mn1;
        float rs0 = 0.f, rs1 = 0.f;
#pragma unroll
        for (int nf = 0; nf < 8; nf++) {
            s[nf][0] = __expf(s[nf][0] - mn0);
            s[nf][1] = __expf(s[nf][1] - mn0);
            s[nf][2] = __expf(s[nf][2] - mn1);
            s[nf][3] = __expf(s[nf][3] - mn1);
            rs0 += s[nf][0] + s[nf][1];
            rs1 += s[nf][2] + s[nf][3];
        }
        rs0 += __shfl_xor_sync(0xffffffffu, rs0, 1);
        rs0 += __shfl_xor_sync(0xffffffffu, rs0, 2);
        rs1 += __shfl_xor_sync(0xffffffffu, rs1, 1);
        rs1 += __shfl_xor_sync(0xffffffffu, rs1, 2);
        l0 = l0 * sc0 + rs0;
        l1 = l1 * sc1 + rs1;
#pragma unroll
        for (int i = 0; i < 8; i++) {
            acc[i][0] *= sc0; acc[i][1] *= sc0;
            acc[i][2] *= sc1; acc[i][3] *= sc1;
        }

        // ---- p *= abm
#pragma unroll
        for (int nf = 0; nf < 8; nf++) {
            float2 t0 = *(float2*)&sM[r0 * SBP + nf * 8 + cc];
            float2 t1 = *(float2*)&sM[(r0 + 8) * SBP + nf * 8 + cc];
            s[nf][0] *= t0.x; s[nf][1] *= t0.y; s[nf][2] *= t1.x; s[nf][3] *= t1.y;
        }

        // ---- acc += P V (3-term)
#pragma unroll
        for (int ks = 0; ks < 4; ks++) {
            uint32_t ahi[4], alo[4];
            split2(s[2 * ks][0],     s[2 * ks][1],     ahi[0], alo[0]);
            split2(s[2 * ks][2],     s[2 * ks][3],     ahi[1], alo[1]);
            split2(s[2 * ks + 1][0], s[2 * ks + 1][1], ahi[2], alo[2]);
            split2(s[2 * ks + 1][2], s[2 * ks + 1][3], ahi[3], alo[3]);
#pragma unroll
            for (int nfd = 0; nfd < 8; nfd++) {
                uint32_t vh2[2], vl2[2];
                uint32_t off = (uint32_t)TSWZ(ks * 16 + vrow, nfd);
                ldm_x2t(vh2, uSm + 16384 + off);
                ldm_x2t(vl2, uSm + 24576 + off);
                mma_bf16(acc[nfd], ahi, vh2);
                mma_bf16(acc[nfd], ahi, vl2);
                mma_bf16(acc[nfd], alo, vh2);
            }
        }
    }

    // ---- epilogue
    float inv0 = 1.0f / l0, inv1 = 1.0f / l1;
    int q0 = qt * 64 + r0;
    size_t o0 = ((size_t)q0 * BB + b) * EE + h * 64;
    size_t o1 = ((size_t)(q0 + 8) * BB + b) * EE + h * 64;
#pragma unroll
    for (int nfd = 0; nfd < 8; nfd++) {
        int dc = nfd * 8 + cc;
        uint32_t h0, lo0, h1, lo1;
        split2(acc[nfd][0] * inv0, acc[nfd][1] * inv0, h0, lo0);
        split2(acc[nfd][2] * inv1, acc[nfd][3] * inv1, h1, lo1);
        *(uint32_t*)(g_ahi + o0 + dc) = h0;
        *(uint32_t*)(g_alo + o0 + dc) = lo0;
        *(uint32_t*)(g_ahi + o1 + dc) = h1;
        *(uint32_t*)(g_alo + o1 + dc) = lo1;
    }
}

// ---------------------------------------------------------------------------
extern "C" void kernel_launch(void* const* d_in, const int* in_sizes, int n_in,
                              void* d_out, int out_size)
{
    (void)in_sizes; (void)n_in; (void)out_size;
    const float* x         = (const float*)d_in[0];
    const float* attn_bias = (const float*)d_in[1];
    const float* attn_mul  = (const float*)d_in[2];
    const int*   kpm       = (const int*)d_in[3];
    const float* W_in      = (const float*)d_in[4];
    const float* b_in      = (const float*)d_in[5];
    const float* W_out     = (const float*)d_in[6];
    const float* b_out     = (const float*)d_in[7];
    float* out = (float*)d_out;

    const int GEMM_SMEM = 81920;
    const int ATTN_SMEM = 67584;
    cudaFuncSetAttribute(gemm_mma<0>, cudaFuncAttributeMaxDynamicSharedMemorySize, GEMM_SMEM);
    cudaFuncSetAttribute(gemm_mma<1>, cudaFuncAttributeMaxDynamicSharedMemorySize, GEMM_SMEM);
    cudaFuncSetAttribute(attn_mma, cudaFuncAttributeMaxDynamicSharedMemorySize, ATTN_SMEM);

    // fp32 -> bf16 hi/lo splits (single launch)
    split_all<<<8192, 256>>>(x, W_in, W_out);

    // QKV projection
    gemm_mma<0><<<dim3(24, 32), 256, GEMM_SMEM>>>(b_in, nullptr);

    // attention
    attn_mma<<<dim3(16, BHH), 128, ATTN_SMEM>>>(attn_bias, attn_mul, kpm);

    // output projection
    gemm_mma<1><<<dim3(8, 32), 256, GEMM_SMEM>>>(b_out, out);
}